// round 2
// baseline (speedup 1.0000x reference)
#include <cuda_runtime.h>
#include <cstdint>

// Problem constants (fixed shapes)
#define T_STEPS 2048
#define BATCH   32
#define HID     512

// ---------------------------------------------------------------------------
// Scratch (device globals; no allocation allowed in kernel_launch)
// ---------------------------------------------------------------------------
__device__ float g_xw [T_STEPS * BATCH * HID];  // input-projection buffer (reused layer 1)
__device__ float g_mid[T_STEPS * BATCH * HID];  // layer-0 output

// ---------------------------------------------------------------------------
// Helpers
// ---------------------------------------------------------------------------
__device__ __forceinline__ uint32_t smem_u32(const void* p) {
    uint32_t a;
    asm("{ .reg .u64 t; cvta.to.shared.u64 t, %1; cvt.u32.u64 %0, t; }"
        : "=r"(a) : "l"(p));
    return a;
}

// Store a float into the same SMEM offset of cluster CTA `rank`.
__device__ __forceinline__ void st_cluster_f32(uint32_t laddr, unsigned rank, float v) {
    asm volatile(
        "{\n\t"
        ".reg .b32 ra;\n\t"
        "mapa.shared::cluster.u32 ra, %0, %1;\n\t"
        "st.shared::cluster.f32 [ra], %2;\n\t"
        "}"
        :: "r"(laddr), "r"(rank), "f"(v) : "memory");
}

__device__ __forceinline__ void cluster_arrive() {
    asm volatile("barrier.cluster.arrive.aligned;" ::: "memory");
}
__device__ __forceinline__ void cluster_wait() {
    asm volatile("barrier.cluster.wait.aligned;" ::: "memory");
}

// ---------------------------------------------------------------------------
// Kernel 1: xw = X(M,512) @ W(512,512)^T + (b1 + b2)        (row K-major both)
//   M = T*B = 65536, N = 512, K = 512
//   Tile: 128(M) x 64(N), BK=16, 256 threads, 8x4 per-thread micro-tile.
// ---------------------------------------------------------------------------
__global__ void __launch_bounds__(256)
gemm_xw_kernel(const float* __restrict__ X,
               const float* __restrict__ W,
               const float* __restrict__ b1,
               const float* __restrict__ b2,
               float* __restrict__ Y)
{
    __shared__ float As[16][132];   // [k][m], padded
    __shared__ float Bs[16][68];    // [k][n], padded

    const int tid = threadIdx.x;
    const int m0 = blockIdx.x * 128;
    const int n0 = blockIdx.y * 64;
    const int ty = tid >> 4;        // 0..15 -> rows ty*8..ty*8+7
    const int tx = tid & 15;        // 0..15 -> cols tx*4..tx*4+3

    // load mapping
    const int am = tid >> 1;        // 0..127
    const int ak = (tid & 1) * 8;   // 0 or 8
    const int bn = tid >> 2;        // 0..63
    const int bk = (tid & 3) * 4;   // 0,4,8,12

    float acc[8][4];
#pragma unroll
    for (int i = 0; i < 8; i++)
#pragma unroll
        for (int j = 0; j < 4; j++) acc[i][j] = 0.f;

    const float* Xr = X + (m0 + am) * 512;
    const float* Wr = W + (n0 + bn) * 512;

    for (int kb = 0; kb < 512; kb += 16) {
        float4 a0 = *(const float4*)(Xr + kb + ak);
        float4 a1 = *(const float4*)(Xr + kb + ak + 4);
        float4 bv = *(const float4*)(Wr + kb + bk);
        __syncthreads();
        As[ak + 0][am] = a0.x; As[ak + 1][am] = a0.y;
        As[ak + 2][am] = a0.z; As[ak + 3][am] = a0.w;
        As[ak + 4][am] = a1.x; As[ak + 5][am] = a1.y;
        As[ak + 6][am] = a1.z; As[ak + 7][am] = a1.w;
        Bs[bk + 0][bn] = bv.x; Bs[bk + 1][bn] = bv.y;
        Bs[bk + 2][bn] = bv.z; Bs[bk + 3][bn] = bv.w;
        __syncthreads();
#pragma unroll
        for (int k = 0; k < 16; k++) {
            float4 a04 = *(const float4*)&As[k][ty * 8];
            float4 a14 = *(const float4*)&As[k][ty * 8 + 4];
            float4 b4  = *(const float4*)&Bs[k][tx * 4];
            float av[8] = {a04.x, a04.y, a04.z, a04.w, a14.x, a14.y, a14.z, a14.w};
            float bw[4] = {b4.x, b4.y, b4.z, b4.w};
#pragma unroll
            for (int i = 0; i < 8; i++)
#pragma unroll
                for (int j = 0; j < 4; j++)
                    acc[i][j] = fmaf(av[i], bw[j], acc[i][j]);
        }
    }

    float bias[4];
#pragma unroll
    for (int j = 0; j < 4; j++)
        bias[j] = b1[n0 + tx * 4 + j] + b2[n0 + tx * 4 + j];

#pragma unroll
    for (int i = 0; i < 8; i++) {
        const int row = m0 + ty * 8 + i;
        float4 o;
        o.x = acc[i][0] + bias[0];
        o.y = acc[i][1] + bias[1];
        o.z = acc[i][2] + bias[2];
        o.w = acc[i][3] + bias[3];
        *(float4*)&Y[row * 512 + n0 + tx * 4] = o;
    }
}

// ---------------------------------------------------------------------------
// Kernel 2: persistent recurrent scan.
//   h_{t+1} = tanh(xw_t + h_t @ Whh^T), out[t] = h_{t+1}
//   Grid = 128 CTAs = 16 clusters of 8 CTAs.
//   Cluster g owns batches {2g, 2g+1}; CTA rank c owns output rows [64c, 64c+64).
//   W_hh slice held in REGISTERS: thread (q, r) owns W[rank*64+r][128q .. 128q+128)
//   as 32 float4 registers, loaded once and reused for all 2048 steps.
//   Per step: FMA-bound matvec (k-split 4), smem reduce, tanh, all-gather of the
//   64x2 slice to all 8 cluster CTAs via st.shared::cluster, split cluster
//   barrier (arrive -> OUT store + next XW prefetch -> wait).
//   h double-buffered in SMEM so one barrier phase per step suffices.
// ---------------------------------------------------------------------------
__global__ void __cluster_dims__(8, 1, 1) __launch_bounds__(256, 1)
rnn_scan_kernel(const float* __restrict__ Whh,
                const float* __restrict__ XW,
                float* __restrict__ OUT)
{
    __shared__ float sH[2][1024];      // double-buffered h: [buf][batch(2)][512]
    __shared__ float sRed[3 * 128];    // k-split partials (q=1..3) x 64 rows x 2 batches

    const int tid = threadIdx.x;
    unsigned rank;
    asm("mov.u32 %0, %%cluster_ctarank;" : "=r"(rank));
    const int group = blockIdx.x >> 3;     // cluster index (blockIdx contiguous in cluster)
    const int b0 = group * 2;              // global batch base

    const int q = tid >> 6;                // k-split 0..3 (k in [128q, 128q+128))
    const int r = tid & 63;                // local row
    const int rowG = (int)rank * 64 + r;   // global output row

    // ---- Load this thread's W slice into registers (one-time, L2-cached) ----
    float4 w[32];
    {
        const float4* Wg = (const float4*)(Whh + (size_t)rowG * 512) + q * 32;
#pragma unroll
        for (int j = 0; j < 32; j++) w[j] = Wg[j];
    }

    // ---- h_0 = 0 ----
    for (int idx = tid; idx < 1024; idx += 256) sH[0][idx] = 0.f;
    __syncthreads();

    // Prefetch xw for t = 0 (only q==0 threads consume it)
    float xv0 = 0.f, xv1 = 0.f;
    if (q == 0) {
        xv0 = XW[(size_t)(0 * BATCH + b0)     * 512 + rowG];
        xv1 = XW[(size_t)(0 * BATCH + b0 + 1) * 512 + rowG];
    }

    for (int t = 0; t < T_STEPS; t++) {
        const float* hc = sH[t & 1];
        float*       hn = sH[(t + 1) & 1];

        // ---- matvec: acc[b] = sum_k W[row][k] * h[b][k] over this thread's k-quarter
        const float4* h0 = (const float4*)hc + q * 32;          // batch b0
        const float4* h1 = (const float4*)(hc + 512) + q * 32;  // batch b0+1
        float acc0 = 0.f, acc1 = 0.f;
#pragma unroll
        for (int j = 0; j < 32; j++) {
            const float4 a = h0[j];
            const float4 b = h1[j];
            acc0 = fmaf(w[j].x, a.x, fmaf(w[j].y, a.y, fmaf(w[j].z, a.z, fmaf(w[j].w, a.w, acc0))));
            acc1 = fmaf(w[j].x, b.x, fmaf(w[j].y, b.y, fmaf(w[j].z, b.z, fmaf(w[j].w, b.w, acc1))));
        }

        // ---- k-split reduction into q==0
        if (q != 0) {
            sRed[((q - 1) * 64 + r) * 2 + 0] = acc0;
            sRed[((q - 1) * 64 + r) * 2 + 1] = acc1;
        }
        __syncthreads();

        float v0 = 0.f, v1 = 0.f;
        if (q == 0) {
#pragma unroll
            for (int s = 0; s < 3; s++) {
                acc0 += sRed[(s * 64 + r) * 2 + 0];
                acc1 += sRed[(s * 64 + r) * 2 + 1];
            }
            v0 = tanhf(acc0 + xv0);
            v1 = tanhf(acc1 + xv1);

            // All-gather our rows into every cluster CTA's h_next (incl. self)
            const uint32_t la0 = smem_u32(hn + rowG);
            const uint32_t la1 = smem_u32(hn + 512 + rowG);
#pragma unroll
            for (unsigned pr = 0; pr < 8; pr++) {
                st_cluster_f32(la0, pr, v0);
                st_cluster_f32(la1, pr, v1);
            }
        }

        // Release DSMEM stores; overlap global traffic with barrier drain.
        cluster_arrive();

        if (q == 0) {
            OUT[(size_t)(t * BATCH + b0)     * 512 + rowG] = v0;
            OUT[(size_t)(t * BATCH + b0 + 1) * 512 + rowG] = v1;
            if (t + 1 < T_STEPS) {
                xv0 = XW[(size_t)((t + 1) * BATCH + b0)     * 512 + rowG];
                xv1 = XW[(size_t)((t + 1) * BATCH + b0 + 1) * 512 + rowG];
            }
        }

        cluster_wait();
    }
}

// ---------------------------------------------------------------------------
// Launch
// ---------------------------------------------------------------------------
extern "C" void kernel_launch(void* const* d_in, const int* in_sizes, int n_in,
                              void* d_out, int out_size)
{
    const float* x    = (const float*)d_in[0];
    const float* wih0 = (const float*)d_in[1];
    const float* whh0 = (const float*)d_in[2];
    const float* bih0 = (const float*)d_in[3];
    const float* bhh0 = (const float*)d_in[4];
    const float* wih1 = (const float*)d_in[5];
    const float* whh1 = (const float*)d_in[6];
    const float* bih1 = (const float*)d_in[7];
    const float* bhh1 = (const float*)d_in[8];
    float* out = (float*)d_out;

    float *xw = nullptr, *mid = nullptr;
    cudaGetSymbolAddress((void**)&xw,  g_xw);
    cudaGetSymbolAddress((void**)&mid, g_mid);

    const dim3 ggrid(512, 8);   // (65536/128) x (512/64)

    // Layer 0
    gemm_xw_kernel<<<ggrid, 256>>>(x,   wih0, bih0, bhh0, xw);
    rnn_scan_kernel<<<128, 256>>>(whh0, xw, mid);
    // Layer 1
    gemm_xw_kernel<<<ggrid, 256>>>(mid, wih1, bih1, bhh1, xw);
    rnn_scan_kernel<<<128, 256>>>(whh1, xw, out);
}

// round 3
// speedup vs baseline: 1.0365x; 1.0365x over previous
#include <cuda_runtime.h>
#include <cstdint>

// Problem constants (fixed shapes)
#define T_STEPS 2048
#define BATCH   32
#define HID     512

// ---------------------------------------------------------------------------
// Scratch (device globals; no allocation allowed in kernel_launch)
// ---------------------------------------------------------------------------
__device__ float g_xw [T_STEPS * BATCH * HID];  // input-projection buffer (reused layer 1)
__device__ float g_mid[T_STEPS * BATCH * HID];  // layer-0 output

// ---------------------------------------------------------------------------
// Helpers
// ---------------------------------------------------------------------------
__device__ __forceinline__ uint32_t smem_u32(const void* p) {
    uint32_t a;
    asm("{ .reg .u64 t; cvta.to.shared.u64 t, %1; cvt.u32.u64 %0, t; }"
        : "=r"(a) : "l"(p));
    return a;
}

// Store a float into the same SMEM offset of cluster CTA `rank`.
__device__ __forceinline__ void st_cluster_f32(uint32_t laddr, unsigned rank, float v) {
    asm volatile(
        "{\n\t"
        ".reg .b32 ra;\n\t"
        "mapa.shared::cluster.u32 ra, %0, %1;\n\t"
        "st.shared::cluster.f32 [ra], %2;\n\t"
        "}"
        :: "r"(laddr), "r"(rank), "f"(v) : "memory");
}

__device__ __forceinline__ void cluster_arrive() {
    asm volatile("barrier.cluster.arrive.aligned;" ::: "memory");
}
__device__ __forceinline__ void cluster_wait() {
    asm volatile("barrier.cluster.wait.aligned;" ::: "memory");
}

// Packed fp32x2 FMA (Blackwell FFMA2): d = a*b + c elementwise on 2 packed floats.
__device__ __forceinline__ unsigned long long fma2(unsigned long long a,
                                                   unsigned long long b,
                                                   unsigned long long c) {
    unsigned long long d;
    asm("fma.rn.f32x2 %0, %1, %2, %3;" : "=l"(d) : "l"(a), "l"(b), "l"(c));
    return d;
}
__device__ __forceinline__ float f2_lo(unsigned long long v) {
    unsigned lo = (unsigned)(v & 0xFFFFFFFFull);
    return __uint_as_float(lo);
}
__device__ __forceinline__ float f2_hi(unsigned long long v) {
    unsigned hi = (unsigned)(v >> 32);
    return __uint_as_float(hi);
}

// ---------------------------------------------------------------------------
// Kernel 1: xw = X(M,512) @ W(512,512)^T + (b1 + b2)        (row K-major both)
//   M = T*B = 65536, N = 512, K = 512
//   Tile: 128(M) x 64(N), BK=16, 256 threads, 8x4 per-thread micro-tile.
//   (unchanged from the passing Round-2 kernel)
// ---------------------------------------------------------------------------
__global__ void __launch_bounds__(256)
gemm_xw_kernel(const float* __restrict__ X,
               const float* __restrict__ W,
               const float* __restrict__ b1,
               const float* __restrict__ b2,
               float* __restrict__ Y)
{
    __shared__ float As[16][132];   // [k][m], padded
    __shared__ float Bs[16][68];    // [k][n], padded

    const int tid = threadIdx.x;
    const int m0 = blockIdx.x * 128;
    const int n0 = blockIdx.y * 64;
    const int ty = tid >> 4;        // 0..15 -> rows ty*8..ty*8+7
    const int tx = tid & 15;        // 0..15 -> cols tx*4..tx*4+3

    // load mapping
    const int am = tid >> 1;        // 0..127
    const int ak = (tid & 1) * 8;   // 0 or 8
    const int bn = tid >> 2;        // 0..63
    const int bk = (tid & 3) * 4;   // 0,4,8,12

    float acc[8][4];
#pragma unroll
    for (int i = 0; i < 8; i++)
#pragma unroll
        for (int j = 0; j < 4; j++) acc[i][j] = 0.f;

    const float* Xr = X + (m0 + am) * 512;
    const float* Wr = W + (n0 + bn) * 512;

    for (int kb = 0; kb < 512; kb += 16) {
        float4 a0 = *(const float4*)(Xr + kb + ak);
        float4 a1 = *(const float4*)(Xr + kb + ak + 4);
        float4 bv = *(const float4*)(Wr + kb + bk);
        __syncthreads();
        As[ak + 0][am] = a0.x; As[ak + 1][am] = a0.y;
        As[ak + 2][am] = a0.z; As[ak + 3][am] = a0.w;
        As[ak + 4][am] = a1.x; As[ak + 5][am] = a1.y;
        As[ak + 6][am] = a1.z; As[ak + 7][am] = a1.w;
        Bs[bk + 0][bn] = bv.x; Bs[bk + 1][bn] = bv.y;
        Bs[bk + 2][bn] = bv.z; Bs[bk + 3][bn] = bv.w;
        __syncthreads();
#pragma unroll
        for (int k = 0; k < 16; k++) {
            float4 a04 = *(const float4*)&As[k][ty * 8];
            float4 a14 = *(const float4*)&As[k][ty * 8 + 4];
            float4 b4  = *(const float4*)&Bs[k][tx * 4];
            float av[8] = {a04.x, a04.y, a04.z, a04.w, a14.x, a14.y, a14.z, a14.w};
            float bw[4] = {b4.x, b4.y, b4.z, b4.w};
#pragma unroll
            for (int i = 0; i < 8; i++)
#pragma unroll
                for (int j = 0; j < 4; j++)
                    acc[i][j] = fmaf(av[i], bw[j], acc[i][j]);
        }
    }

    float bias[4];
#pragma unroll
    for (int j = 0; j < 4; j++)
        bias[j] = b1[n0 + tx * 4 + j] + b2[n0 + tx * 4 + j];

#pragma unroll
    for (int i = 0; i < 8; i++) {
        const int row = m0 + ty * 8 + i;
        float4 o;
        o.x = acc[i][0] + bias[0];
        o.y = acc[i][1] + bias[1];
        o.z = acc[i][2] + bias[2];
        o.w = acc[i][3] + bias[3];
        *(float4*)&Y[row * 512 + n0 + tx * 4] = o;
    }
}

// ---------------------------------------------------------------------------
// Kernel 2: persistent recurrent scan.
//   h_{t+1} = tanh(xw_t + h_t @ Whh^T), out[t] = h_{t+1}
//   Grid = 128 CTAs = 16 clusters of 8 CTAs.
//   Cluster g owns batches {2g, 2g+1}; CTA rank c owns output rows [64c, 64c+64).
//   W_hh slice held in REGISTERS (128 floats/thread, loaded once).
//   Matvec uses packed fma.rn.f32x2 paired over k: 128 FFMA2/thread/step
//   (vs 256 scalar FFMA) -> halves the FMA-pipe issue floor.
//   All 4 k-split groups dump partials to smem; 128 threads then each own one
//   (row, batch) output: 4-way sum + xw + tanh + all-gather to 8 cluster CTAs
//   via st.shared::cluster. Split cluster barrier (arrive -> OUT store + next
//   XW prefetch -> wait). h double-buffered in SMEM.
// ---------------------------------------------------------------------------
__global__ void __cluster_dims__(8, 1, 1) __launch_bounds__(256, 1)
rnn_scan_kernel(const float* __restrict__ Whh,
                const float* __restrict__ XW,
                float* __restrict__ OUT)
{
    __shared__ float sH[2][1024];        // double-buffered h: [buf][batch(2)][512]
    __shared__ float sRed[4 * 64 * 2];   // k-split partials: [q][row][batch]

    const int tid = threadIdx.x;
    unsigned rank;
    asm("mov.u32 %0, %%cluster_ctarank;" : "=r"(rank));
    const int group = blockIdx.x >> 3;     // cluster index (blockIdx contiguous in cluster)
    const int b0 = group * 2;              // global batch base

    const int q = tid >> 6;                // k-split 0..3 (k in [128q, 128q+128))
    const int r = tid & 63;                // local row (matvec role)
    const int rowG = (int)rank * 64 + r;   // global output row (matvec role)

    // ---- Load this thread's W slice into registers (one-time, L2-cached) ----
    // 128 floats = 32 ulonglong2 (each .x/.y holds a packed f32x2 pair over k).
    ulonglong2 w[32];
    {
        const ulonglong2* Wg = (const ulonglong2*)(Whh + (size_t)rowG * 512) + q * 32;
#pragma unroll
        for (int j = 0; j < 32; j++) w[j] = Wg[j];
    }

    // ---- Tail role: thread tid<128 owns output (tr, tb) ----
    const int tr  = tid >> 1;              // 0..63   (row)
    const int tb  = tid & 1;               // 0..1    (batch)
    const int trowG = (int)rank * 64 + tr;

    // ---- h_0 = 0 ----
    for (int idx = tid; idx < 2048; idx += 256) sH[0][idx & 1023] = 0.f;  // zero buf0 twice-safe
    __syncthreads();

    // Prefetch xw for t = 0 (tail threads only)
    float xv = 0.f;
    if (tid < 128)
        xv = XW[(size_t)(0 * BATCH + b0 + tb) * 512 + trowG];

    for (int t = 0; t < T_STEPS; t++) {
        const float* hc = sH[t & 1];
        float*       hn = sH[(t + 1) & 1];

        // ---- matvec: acc[b] = sum_k W[row][k] * h[b][k] over this thread's k-quarter
        // k-paired packed FMA: 32 iters x (2 pairs) x (2 batches) = 128 FFMA2.
        const ulonglong2* h0 = (const ulonglong2*)hc + q * 32;          // batch b0
        const ulonglong2* h1 = (const ulonglong2*)(hc + 512) + q * 32;  // batch b0+1
        unsigned long long a0x = 0, a0y = 0, a1x = 0, a1y = 0;  // packed (even,odd) accs
#pragma unroll
        for (int j = 0; j < 32; j++) {
            const ulonglong2 ha = h0[j];
            const ulonglong2 hb = h1[j];
            a0x = fma2(w[j].x, ha.x, a0x);
            a0y = fma2(w[j].y, ha.y, a0y);
            a1x = fma2(w[j].x, hb.x, a1x);
            a1y = fma2(w[j].y, hb.y, a1y);
        }
        const float acc0 = (f2_lo(a0x) + f2_hi(a0x)) + (f2_lo(a0y) + f2_hi(a0y));
        const float acc1 = (f2_lo(a1x) + f2_hi(a1x)) + (f2_lo(a1y) + f2_hi(a1y));

        // ---- all k-split groups dump partials: sRed[q][r][b]
        *(float2*)&sRed[(q * 64 + r) * 2] = make_float2(acc0, acc1);
        __syncthreads();

        // ---- 128-thread tail: sum 4 partials, tanh, all-gather
        float v = 0.f;
        if (tid < 128) {
            float s = sRed[(0 * 64 + tr) * 2 + tb];
            s += sRed[(1 * 64 + tr) * 2 + tb];
            s += sRed[(2 * 64 + tr) * 2 + tb];
            s += sRed[(3 * 64 + tr) * 2 + tb];
            v = tanhf(s + xv);

            // All-gather our element into every cluster CTA's h_next (incl. self)
            const uint32_t la = smem_u32(hn + tb * 512 + trowG);
#pragma unroll
            for (unsigned pr = 0; pr < 8; pr++)
                st_cluster_f32(la, pr, v);
        }

        // Release DSMEM stores; overlap global traffic with barrier drain.
        cluster_arrive();

        if (tid < 128) {
            OUT[(size_t)(t * BATCH + b0 + tb) * 512 + trowG] = v;
            if (t + 1 < T_STEPS)
                xv = XW[(size_t)((t + 1) * BATCH + b0 + tb) * 512 + trowG];
        }

        cluster_wait();
    }
}

// ---------------------------------------------------------------------------
// Launch
// ---------------------------------------------------------------------------
extern "C" void kernel_launch(void* const* d_in, const int* in_sizes, int n_in,
                              void* d_out, int out_size)
{
    const float* x    = (const float*)d_in[0];
    const float* wih0 = (const float*)d_in[1];
    const float* whh0 = (const float*)d_in[2];
    const float* bih0 = (const float*)d_in[3];
    const float* bhh0 = (const float*)d_in[4];
    const float* wih1 = (const float*)d_in[5];
    const float* whh1 = (const float*)d_in[6];
    const float* bih1 = (const float*)d_in[7];
    const float* bhh1 = (const float*)d_in[8];
    float* out = (float*)d_out;

    float *xw = nullptr, *mid = nullptr;
    cudaGetSymbolAddress((void**)&xw,  g_xw);
    cudaGetSymbolAddress((void**)&mid, g_mid);

    const dim3 ggrid(512, 8);   // (65536/128) x (512/64)

    // Layer 0
    gemm_xw_kernel<<<ggrid, 256>>>(x,   wih0, bih0, bhh0, xw);
    rnn_scan_kernel<<<128, 256>>>(whh0, xw, mid);
    // Layer 1
    gemm_xw_kernel<<<ggrid, 256>>>(mid, wih1, bih1, bhh1, xw);
    rnn_scan_kernel<<<128, 256>>>(whh1, xw, out);
}